// round 14
// baseline (speedup 1.0000x reference)
#include <cuda_runtime.h>
#include <math.h>

#define BB 64
#define SS 2048
#define NC 128
#define NH 512
#define NINP 34
#define TT 400
#define G4 (4*NH)
#define NBLK 128
#define NTHR 512
#define NW 16
#define GN_TOTAL (TT*BB*NINP)
#define XS_STRIDE 68   // floats; 272 B rows -> 16B-aligned float4/ull2 reads

typedef unsigned long long ull;

// ---------------- device scratch (static, no runtime allocs) ----------------
__device__ float d_h[3][BB*NH];
__device__ float d_c[3][BB*NH];
__device__ float d_gp[8][BB*G4];      // per-K-split GEMM partials
__device__ float d_x[BB*2*NC];        // [emb[tok], ctx] per b
__device__ float d_pmax[BB*2];
__device__ float d_psum[BB*2];
__device__ float d_ctxp[2][BB*NC];
__device__ float d_gn[GN_TOTAL];
__device__ unsigned int bar_cnt;       // returns to 0 every barrier
__device__ unsigned int bar_gen;       // monotonic across replays
__device__ unsigned int d_jcnt[3][16]; // per (layer, jtile) arrival counters (monotonic)
__device__ unsigned int d_pflag[BB][2];// pair sync flags (monotonic)

// ---------------- packed f32x2 helpers (Blackwell FFMA2) ----------------
__device__ __forceinline__ ull pack2(float lo, float hi) {
    ull r;
    asm("mov.b64 %0, {%1, %2};" : "=l"(r) : "r"(__float_as_uint(lo)), "r"(__float_as_uint(hi)));
    return r;
}
__device__ __forceinline__ void unpack2(ull v, float &lo, float &hi) {
    unsigned int a, b;
    asm("mov.b64 {%0, %1}, %2;" : "=r"(a), "=r"(b) : "l"(v));
    lo = __uint_as_float(a); hi = __uint_as_float(b);
}
__device__ __forceinline__ void ffma2(ull &d, ull a, ull b) {
    asm("fma.rn.f32x2 %0, %1, %2, %0;" : "+l"(d) : "l"(a), "l"(b));
}

// ---------------- grid barrier: release fence only; acquire via .cg reads ----
__device__ __forceinline__ void gridbar() {
    __syncthreads();
    __threadfence();            // release: drain this thread's stores to L2
    __syncthreads();            // all threads fenced before arrival
    if (threadIdx.x == 0) {
        unsigned int g = *(volatile unsigned int*)&bar_gen;
        if (atomicAdd(&bar_cnt, 1u) == NBLK - 1u) {
            *(volatile unsigned int*)&bar_cnt = 0u;
            __threadfence();
            atomicAdd(&bar_gen, 1u);
        } else {
            while (*(volatile unsigned int*)&bar_gen == g) { __nanosleep(32); }
        }
    }
    __syncthreads();
    // no acquire fence: all cross-CTA data reads below use __ldcg (L2 direct)
}

#define WARP_RED_SUM(p) { _Pragma("unroll") for (int _o = 16; _o; _o >>= 1) (p) += __shfl_xor_sync(0xffffffffu, (p), _o); }

__global__ void __launch_bounds__(NTHR) decoder_persistent(
    const float* __restrict__ keys, const float* __restrict__ values,
    const int* __restrict__ lens, const int* __restrict__ inputs,
    const float* __restrict__ emb,
    const float* __restrict__ wq, const float* __restrict__ bq,
    const float* __restrict__ wc, const float* __restrict__ bc,
    const float* __restrict__ b_out,
    const float* __restrict__ w0ih, const float* __restrict__ w0hh,
    const float* __restrict__ b0ih, const float* __restrict__ b0hh,
    const float* __restrict__ h00, const float* __restrict__ c00,
    const float* __restrict__ w1ih, const float* __restrict__ w1hh,
    const float* __restrict__ b1ih, const float* __restrict__ b1hh,
    const float* __restrict__ h01, const float* __restrict__ c01,
    const float* __restrict__ w2ih, const float* __restrict__ w2hh,
    const float* __restrict__ b2ih, const float* __restrict__ b2hh,
    const float* __restrict__ h02, const float* __restrict__ c02,
    float* __restrict__ logits_out, float* __restrict__ att_out,
    float* __restrict__ gen_out)
{
    // smem (aliased per phase):
    // GEMM: xs = [16][68] floats @0 (4352 B), ws2 = [16][133] ull @4352 (17024 B)
    // ATT:  q @0, en @128(1024), red @1152, cp @1200(2048), ctxs @3248, z @3392, lg @3536 (floats)
    __shared__ __align__(16) char SB[21504];
    __shared__ int sflag;
    float* SF = (float*)SB;
    const int blk = blockIdx.x, tid = threadIdx.x;
    const int w = tid >> 5, lane = tid & 31;

    // ---- init h/c + gumbel noise ----
    for (int i = blk*NTHR + tid; i < 3*BB*NH; i += NBLK*NTHR) {
        int l = i / (BB*NH), r = i % (BB*NH), u = r % NH;
        const float* hs = (l == 0) ? h00 : (l == 1) ? h01 : h02;
        const float* cs = (l == 0) ? c00 : (l == 1) ? c01 : c02;
        d_h[l][r] = hs[u];
        d_c[l][r] = cs[u];
    }
    // JAX partitionable threefry: counter j -> (0, j), key (0,1), bits = y0^y1
    for (int j = blk*NTHR + tid; j < GN_TOTAL; j += NBLK*NTHR) {
        unsigned int x0 = 0u;
        unsigned int x1 = (unsigned int)j;
        const unsigned int k0 = 0u, k1 = 1u;
        const unsigned int k2 = 0x1BD11BDAu ^ k0 ^ k1;
        x0 += k0; x1 += k1;
#define TF_RND(r) { x0 += x1; x1 = (x1 << (r)) | (x1 >> (32-(r))); x1 ^= x0; }
        TF_RND(13) TF_RND(15) TF_RND(26) TF_RND(6)
        x0 += k1; x1 += k2 + 1u;
        TF_RND(17) TF_RND(29) TF_RND(16) TF_RND(24)
        x0 += k2; x1 += k0 + 2u;
        TF_RND(13) TF_RND(15) TF_RND(26) TF_RND(6)
        x0 += k0; x1 += k1 + 3u;
        TF_RND(17) TF_RND(29) TF_RND(16) TF_RND(24)
        x0 += k1; x1 += k2 + 4u;
        TF_RND(13) TF_RND(15) TF_RND(26) TF_RND(6)
        x0 += k2; x1 += k0 + 5u;
#undef TF_RND
        unsigned int bits = x0 ^ x1;
        float u = __uint_as_float((bits >> 9) | 0x3f800000u) - 1.0f;
        d_gn[j] = -logf(1e-10f - logf(u + 1e-10f));
    }
    gridbar();
    // epoch base for pair flags (uniform across grid; no gridbar can complete
    // before every CTA has read this, since the next gridbar is after finalize)
    const unsigned int base = *(volatile unsigned int*)&bar_gen;

    const float* WihA[3] = {w0ih, w1ih, w2ih};
    const float* WhhA[3] = {w0hh, w1hh, w2hh};
    const float* BihA[3] = {b0ih, b1ih, b2ih};
    const float* BhhA[3] = {b0hh, b1hh, b2hh};

    const int b_att = blk >> 1;
    const int sub   = blk & 1;

    for (int t = -1; t < TT; t++) {
        if (t >= 0) {
#pragma unroll
            for (int l = 0; l < 3; l++) {
                // ===== fused GEMM + finisher-cell, one gridbar per layer =====
                const int split = blk & 7, jt = blk >> 3;     // 8 splits x 16 jtiles
                const int u0 = jt * 32;                        // unit slice [u0, u0+32)
                const int K1 = (l == 0) ? 2*NC : NH;
                const int Kchunk = (K1 + NH) >> 3;             // 96 or 128
                const int kb0 = split * Kchunk;
                const float* xin = (l == 0) ? d_x : d_h[l-1];
                const float* hin = d_h[l];
                const float* Wih = WihA[l];
                const float* Whh = WhhA[l];
                float* xs = SF;                       // [16][68]
                ull*   ws2 = (ull*)(SB + 4352);       // [16][133] (w duplicated)
                const int tx = tid & 31, ty = tid >> 5;

                ull a0[4], a1[4];
#pragma unroll
                for (int jj = 0; jj < 4; jj++) { a0[jj] = 0ull; a1[jj] = 0ull; }

                for (int kt = 0; kt < Kchunk; kt += 16) {
                    const int kb = kb0 + kt;
                    for (int i = tid; i < 1024; i += NTHR) {
                        int kk = i & 15, bb = i >> 4;
                        int k = kb + kk;
                        float v = (k < K1) ? __ldcg(xin + bb*K1 + k)
                                           : __ldcg(hin + bb*NH + (k - K1));
                        xs[kk*XS_STRIDE + bb] = v;
                    }
                    for (int i = tid; i < 2048; i += NTHR) {
                        int kk = i & 15, jl = i >> 4;
                        int grow = (jl >> 5)*NH + u0 + (jl & 31);  // gate row
                        int k = kb + kk;
                        float v = (k < K1) ? Wih[(size_t)grow*K1 + k]
                                           : Whh[(size_t)grow*NH + (k - K1)];
                        ws2[kk*133 + jl] = pack2(v, v);
                    }
                    __syncthreads();
#pragma unroll
                    for (int kk = 0; kk < 16; kk++) {
                        ulonglong2 xv = *(ulonglong2*)(xs + kk*XS_STRIDE + ty*4);
#pragma unroll
                        for (int jj = 0; jj < 4; jj++) {
                            ull ww = ws2[kk*133 + jj*32 + tx];
                            ffma2(a0[jj], xv.x, ww);
                            ffma2(a1[jj], xv.y, ww);
                        }
                    }
                    __syncthreads();
                }
                {
                    float* gp = d_gp[split];
#pragma unroll
                    for (int jj = 0; jj < 4; jj++) {
                        int gate = jj*NH + u0 + tx;            // jj = gate type
                        float f0, f1, f2, f3;
                        unpack2(a0[jj], f0, f1);
                        unpack2(a1[jj], f2, f3);
                        __stcg(gp + (size_t)(ty*4 + 0)*G4 + gate, f0);
                        __stcg(gp + (size_t)(ty*4 + 1)*G4 + gate, f1);
                        __stcg(gp + (size_t)(ty*4 + 2)*G4 + gate, f2);
                        __stcg(gp + (size_t)(ty*4 + 3)*G4 + gate, f3);
                    }
                }
                __threadfence();     // release partials
                __syncthreads();
                if (tid == 0) {
                    unsigned int old = atomicAdd(&d_jcnt[l][jt], 1u);
                    sflag = (((old + 1u) & 7u) == 0u) ? 1 : 0;
                }
                __syncthreads();
                if (sflag) {
                    // last split of this jtile: do the cell for units [u0,u0+32)
                    const float* bih = BihA[l];
                    const float* bhh = BhhA[l];
                    const int uu = tid & 31;
                    const int u  = u0 + uu;
                    const float bi = bih[u]        + bhh[u];
                    const float bf = bih[u + NH]   + bhh[u + NH];
                    const float bg = bih[u + 2*NH] + bhh[u + 2*NH];
                    const float bo = bih[u + 3*NH] + bhh[u + 3*NH];
#pragma unroll
                    for (int s = 0; s < 4; s++) {
                        const int b = s*16 + (tid >> 5);
                        float gi = bi, gf = bf, gg = bg, go = bo;
#pragma unroll
                        for (int sp = 0; sp < 8; sp++) {
                            const float* gpp = d_gp[sp] + (size_t)b*G4 + u0 + uu;
                            gi += __ldcg(gpp);
                            gf += __ldcg(gpp + NH);
                            gg += __ldcg(gpp + 2*NH);
                            go += __ldcg(gpp + 3*NH);
                        }
                        float si = 1.0f / (1.0f + expf(-gi));
                        float sf = 1.0f / (1.0f + expf(-gf));
                        float so = 1.0f / (1.0f + expf(-go));
                        const int idx = b*NH + u;
                        float cn = sf * __ldcg(&d_c[l][idx]) + si * tanhf(gg);
                        __stcg(&d_c[l][idx], cn);
                        __stcg(&d_h[l][idx], so * tanhf(cn));
                    }
                }
                gridbar();
            }
        }

        const int len   = lens[b_att];
        const int h0l   = len >> 1;
        const int begin = sub ? h0l : 0;
        const int cnt   = sub ? (len - h0l) : h0l;
        const float* h3 = d_h[2] + (size_t)b_att*NH;

        // ===== attention: q-proj + energies + local softmax + ctx partial =====
        {
            float* q   = SF;
            float* en  = SF + 128;
            float* red = SF + 1152;
            float* cp  = SF + 1200;

            for (int d = w; d < NC; d += NW) {
                float p = 0.f;
                const float* wr = wq + (size_t)d*NH;
#pragma unroll 4
                for (int i = lane; i < NH; i += 32) p = fmaf(__ldcg(h3 + i), wr[i], p);
                WARP_RED_SUM(p);
                if (lane == 0) q[d] = p + bq[d];
            }
            __syncthreads();
            float4 q4 = ((const float4*)q)[lane];
            const float4* kp = (const float4*)(keys + (size_t)b_att*SS*NC)
                               + (size_t)begin*32 + lane;
            float bmax = -1e30f;
            for (int ib = 0; ib < 8; ib++) {
                const int basr = ib*128 + w*8;
                float4 kv[8];
#pragma unroll
                for (int j = 0; j < 8; j++) {
                    int r = basr + j;
                    kv[j] = (r < cnt) ? __ldcg(kp + (size_t)r*32)
                                      : make_float4(0.f, 0.f, 0.f, 0.f);
                }
#pragma unroll
                for (int j = 0; j < 8; j++) {
                    int r = basr + j;
                    float p = fmaf(q4.x, kv[j].x, fmaf(q4.y, kv[j].y,
                              fmaf(q4.z, kv[j].z, q4.w*kv[j].w)));
                    WARP_RED_SUM(p);
                    if (r < cnt) {
                        if (lane == 0) en[r] = p;
                        bmax = fmaxf(bmax, p);
                    }
                }
            }
            if (lane == 0) red[w] = bmax;
            __syncthreads();
            if (tid == 0) {
                float m = red[0];
                for (int i = 1; i < NW; i++) m = fmaxf(m, red[i]);
                red[16] = m;
            }
            __syncthreads();
            const float m_loc = red[16];

            const float4* vp = (const float4*)(values + (size_t)b_att*SS*NC)
                               + (size_t)begin*32 + lane;
            float4 ca0 = make_float4(0.f, 0.f, 0.f, 0.f);
            float4 ca1 = make_float4(0.f, 0.f, 0.f, 0.f);
            float ps = 0.f;
            for (int ib = 0; ib < 8; ib++) {
                const int basr = ib*128 + w*8;
                float4 vv[8];
                float ee[8];
#pragma unroll
                for (int j = 0; j < 8; j++) {
                    int r = basr + j;
                    vv[j] = (r < cnt) ? __ldcg(vp + (size_t)r*32)
                                      : make_float4(0.f, 0.f, 0.f, 0.f);
                }
#pragma unroll
                for (int j = 0; j < 8; j++) {
                    int r = basr + j;
                    float e = (r < cnt) ? expf(en[r] - m_loc) : 0.f;
                    ee[j] = e;
                    ps += e;
                }
                if (lane == 0) {
#pragma unroll
                    for (int j = 0; j < 8; j++) {
                        int r = basr + j;
                        if (r < cnt) en[r] = ee[j];
                    }
                }
#pragma unroll
                for (int j = 0; j < 8; j++) {
                    if (j & 1) {
                        ca1.x = fmaf(ee[j], vv[j].x, ca1.x);
                        ca1.y = fmaf(ee[j], vv[j].y, ca1.y);
                        ca1.z = fmaf(ee[j], vv[j].z, ca1.z);
                        ca1.w = fmaf(ee[j], vv[j].w, ca1.w);
                    } else {
                        ca0.x = fmaf(ee[j], vv[j].x, ca0.x);
                        ca0.y = fmaf(ee[j], vv[j].y, ca0.y);
                        ca0.z = fmaf(ee[j], vv[j].z, ca0.z);
                        ca0.w = fmaf(ee[j], vv[j].w, ca0.w);
                    }
                }
            }
            float4 ca = make_float4(ca0.x + ca1.x, ca0.y + ca1.y,
                                    ca0.z + ca1.z, ca0.w + ca1.w);
            if (lane == 0) red[w] = ps;
            ((float4*)cp)[w*32 + lane] = ca;
            __syncthreads();
            if (tid == 0) {
                float sm = 0.f;
                for (int i = 0; i < NW; i++) sm += red[i];
                d_psum[2*b_att + sub] = sm;
                d_pmax[2*b_att + sub] = m_loc;
            }
            if (tid < NC) {
                float cv = 0.f;
#pragma unroll
                for (int i = 0; i < NW; i++) cv += cp[i*128 + tid];
                d_ctxp[sub][b_att*NC + tid] = cv;
            }
            // zero-fill masked att_out region (independent of partner)
            if (t >= 0) {
                float* ao = att_out + ((size_t)t*BB + b_att)*SS;
                int zlen  = SS - len;
                int zhalf = zlen >> 1;
                int zb    = len + sub*zhalf;
                int zc    = sub ? (zlen - zhalf) : zhalf;
                for (int i = tid; i < zc; i += NTHR)
                    __stcs(ao + zb + i, 0.f);
            }
        }

        // ===== pair sync (only the 2 CTAs of this batch row) =====
        {
            const unsigned int seq = base + (unsigned int)(t + 2);
            __syncthreads();
            __threadfence();     // release pmax/psum/ctxp
            __syncthreads();
            if (tid == 0) {
                *(volatile unsigned int*)&d_pflag[b_att][sub] = seq;
                while (*(volatile unsigned int*)&d_pflag[b_att][1 - sub] < seq)
                    { __nanosleep(32); }
            }
            __syncthreads();
        }

        // ===== finalize: rescale + att write + ctx + out head + pack x =====
        {
            float m0 = __ldcg(&d_pmax[2*b_att]), m1 = __ldcg(&d_pmax[2*b_att + 1]);
            float m = fmaxf(m0, m1);
            float e0 = expf(m0 - m), e1 = expf(m1 - m);
            float total = __ldcg(&d_psum[2*b_att])*e0 + __ldcg(&d_psum[2*b_att + 1])*e1;
            float inv = 1.0f / total;
            float f = ((sub == 0) ? e0 : e1) * inv;
            float* en = SF + 128;
            if (t >= 0) {
                float* ao = att_out + ((size_t)t*BB + b_att)*SS;
                for (int i = tid; i < cnt; i += NTHR)
                    __stcs(ao + begin + i, en[i] * f);
            }
            if (sub == 0) {
                float* ctxs = SF + 3248;
                float* z    = SF + 3392;
                float* lg   = SF + 3536;
                if (tid < NC) {
                    float cv = (__ldcg(&d_ctxp[0][b_att*NC + tid])*e0
                              + __ldcg(&d_ctxp[1][b_att*NC + tid])*e1) * inv;
                    ctxs[tid] = cv;
                    __stcg(&d_x[b_att*2*NC + NC + tid], cv);
                    if (t + 1 < TT) {
                        int tok = inputs[(size_t)b_att*TT + (t + 1)];
                        __stcg(&d_x[b_att*2*NC + tid], emb[(size_t)tok*NC + tid]);
                    }
                }
                __syncthreads();
                if (t >= 0) {
                    for (int d = w; d < NC; d += NW) {
                        float p = 0.f;
                        const float* wr = wc + (size_t)d*(NH + NC);
#pragma unroll 4
                        for (int i = lane; i < NH + NC; i += 32) {
                            float xv = (i < NH) ? __ldcg(h3 + i) : ctxs[i - NH];
                            p = fmaf(xv, wr[i], p);
                        }
                        WARP_RED_SUM(p);
                        if (lane == 0) {
                            float a = p + bc[d];
                            z[d] = (a > 0.f) ? a : 0.01f * a;
                        }
                    }
                    __syncthreads();
                    if (tid < NINP) {
                        float lv = b_out[tid];
                        const float* er = emb + (size_t)tid*NC;
#pragma unroll 4
                        for (int k = 0; k < NC; k++) lv = fmaf(z[k], er[k], lv);
                        logits_out[((size_t)t*BB + b_att)*NINP + tid] = lv;
                        lg[tid] = lv + d_gn[((size_t)t*BB + b_att)*NINP + tid];
                    }
                    __syncthreads();
                    if (tid == 0) {
                        float best = lg[0]; int bi = 0;
                        for (int i = 1; i < NINP; i++)
                            if (lg[i] > best) { best = lg[i]; bi = i; }
                        gen_out[(size_t)t*BB + b_att] = (float)bi;
                    }
                }
            }
        }
        gridbar();
    }
}

// ---------------- launch: ONE graph node ----------------
extern "C" void kernel_launch(void* const* d_in, const int* in_sizes, int n_in,
                              void* d_out, int out_size)
{
    const float* keys   = (const float*)d_in[0];
    const float* values = (const float*)d_in[1];
    const int*   lens   = (const int*)d_in[2];
    const int*   inputs = (const int*)d_in[3];
    const float* emb    = (const float*)d_in[4];
    const float* wq     = (const float*)d_in[5];
    const float* bq     = (const float*)d_in[6];
    const float* wc     = (const float*)d_in[7];
    const float* bc     = (const float*)d_in[8];
    const float* b_out  = (const float*)d_in[9];

    float* O = (float*)d_out;
    float* logits_out = O;
    float* att_out    = O + (size_t)TT*BB*NINP;
    float* gen_out    = att_out + (size_t)TT*BB*SS;

    decoder_persistent<<<NBLK, NTHR>>>(
        keys, values, lens, inputs, emb, wq, bq, wc, bc, b_out,
        (const float*)d_in[10], (const float*)d_in[11], (const float*)d_in[12],
        (const float*)d_in[13], (const float*)d_in[14], (const float*)d_in[15],
        (const float*)d_in[16], (const float*)d_in[17], (const float*)d_in[18],
        (const float*)d_in[19], (const float*)d_in[20], (const float*)d_in[21],
        (const float*)d_in[22], (const float*)d_in[23], (const float*)d_in[24],
        (const float*)d_in[25], (const float*)d_in[26], (const float*)d_in[27],
        logits_out, att_out, gen_out);
}

// round 15
// speedup vs baseline: 1.5013x; 1.5013x over previous
#include <cuda_runtime.h>
#include <math.h>

#define BB 64
#define SS 2048
#define NC 128
#define NH 512
#define NINP 34
#define TT 400
#define G4 (4*NH)
#define NBLK 128
#define NTHR 512
#define NW 16
#define GN_TOTAL (TT*BB*NINP)
#define XS_STRIDE 68   // 272 B rows: 16B-aligned float4 reads

// persistent-weight smem layout (floats)
#define W0_OFF 0        // layer0: 6 groups x 16x133 = 12768
#define W1_OFF 12768    // layer1: 8 groups x 16x133 = 17024
#define W2_OFF 29792    // layer2: 8 groups x 16x133 = 17024
#define SCR_OFF 46816   // phase scratch (xs / attention), 3584 floats
#define SMEM_FLOATS (SCR_OFF + 3584)
#define SMEM_BYTES (SMEM_FLOATS * 4)

typedef unsigned long long ull;

// ---------------- device scratch (static, no runtime allocs) ----------------
__device__ float d_h[3][BB*NH];
__device__ float d_c[3][BB*NH];
__device__ float d_gp[8][BB*G4];      // per-K-split GEMM partials
__device__ float d_x[BB*2*NC];        // [emb[tok], ctx] per b
__device__ float d_pmax[BB*2];
__device__ float d_psum[BB*2];
__device__ float d_ctxp[2][BB*NC];
__device__ float d_gn[GN_TOTAL];
__device__ unsigned int bar_cnt;      // zero-init; returns to 0 every launch
__device__ unsigned int bar_gen;      // monotonic across replays

// ---------------- packed f32x2 helpers (Blackwell FFMA2) ----------------
__device__ __forceinline__ ull pack2(float lo, float hi) {
    ull r;
    asm("mov.b64 %0, {%1, %2};" : "=l"(r) : "r"(__float_as_uint(lo)), "r"(__float_as_uint(hi)));
    return r;
}
__device__ __forceinline__ void unpack2(ull v, float &lo, float &hi) {
    unsigned int a, b;
    asm("mov.b64 {%0, %1}, %2;" : "=r"(a), "=r"(b) : "l"(v));
    lo = __uint_as_float(a); hi = __uint_as_float(b);
}
__device__ __forceinline__ void ffma2(ull &d, ull a, ull b) {
    asm("fma.rn.f32x2 %0, %1, %2, %0;" : "+l"(d) : "l"(a), "l"(b));
}

// ---------------- software grid barrier (all 128 CTAs resident) ----------------
__device__ __forceinline__ void gridbar() {
    __syncthreads();
    __threadfence();            // release
    __syncthreads();
    if (threadIdx.x == 0) {
        unsigned int g = *(volatile unsigned int*)&bar_gen;
        if (atomicAdd(&bar_cnt, 1u) == NBLK - 1u) {
            *(volatile unsigned int*)&bar_cnt = 0u;
            __threadfence();
            atomicAdd(&bar_gen, 1u);
        } else {
            while (*(volatile unsigned int*)&bar_gen == g) { __nanosleep(64); }
        }
        __threadfence();        // acquire
    }
    __syncthreads();
}

#define WARP_RED_SUM(p) { _Pragma("unroll") for (int _o = 16; _o; _o >>= 1) (p) += __shfl_xor_sync(0xffffffffu, (p), _o); }

extern __shared__ float DS[];

__global__ void __launch_bounds__(NTHR) decoder_persistent(
    const float* __restrict__ keys, const float* __restrict__ values,
    const int* __restrict__ lens, const int* __restrict__ inputs,
    const float* __restrict__ emb,
    const float* __restrict__ wq, const float* __restrict__ bq,
    const float* __restrict__ wc, const float* __restrict__ bc,
    const float* __restrict__ b_out,
    const float* __restrict__ w0ih, const float* __restrict__ w0hh,
    const float* __restrict__ b0ih, const float* __restrict__ b0hh,
    const float* __restrict__ h00, const float* __restrict__ c00,
    const float* __restrict__ w1ih, const float* __restrict__ w1hh,
    const float* __restrict__ b1ih, const float* __restrict__ b1hh,
    const float* __restrict__ h01, const float* __restrict__ c01,
    const float* __restrict__ w2ih, const float* __restrict__ w2hh,
    const float* __restrict__ b2ih, const float* __restrict__ b2hh,
    const float* __restrict__ h02, const float* __restrict__ c02,
    float* __restrict__ logits_out, float* __restrict__ att_out,
    float* __restrict__ gen_out)
{
    // DS: [0..46816) persistent weight slices; [46816..50400) phase scratch:
    // GEMM: xs = SCR[0..1088)  [16][68]
    // ATT:  q = SCR[0..128), en = SCR[128..1152), red = SCR[1152..1169),
    //       cp = SCR[1200..3248), ctxs = SCR[3248..3376), z = SCR[3392..3520), lg = SCR[3536..)
    float* SCR = DS + SCR_OFF;
    const int blk = blockIdx.x, tid = threadIdx.x;
    const int w = tid >> 5, lane = tid & 31;

    const float* WihA[3] = {w0ih, w1ih, w2ih};
    const float* WhhA[3] = {w0hh, w1hh, w2hh};
    const float* BihA[3] = {b0ih, b1ih, b2ih};
    const float* BhhA[3] = {b0hh, b1hh, b2hh};
    const int WOFF[3] = {W0_OFF, W1_OFF, W2_OFF};

    // ---- preload this CTA's weight slices into persistent smem (once) ----
    {
        const int split = blk & 7, jt = blk >> 3;
        const int u0g = jt * 128;
#pragma unroll
        for (int l = 0; l < 3; l++) {
            const int K1 = (l == 0) ? 2*NC : NH;
            const int Kchunk = (K1 + NH) >> 3;       // 96 or 128
            const int kb0 = split * Kchunk;
            const float* Wih = WihA[l];
            const float* Whh = WhhA[l];
            float* wsl = DS + WOFF[l];
            for (int g = 0; g < (Kchunk >> 4); g++) {
                const int kb = kb0 + g*16;
                for (int i = tid; i < 2048; i += NTHR) {
                    int kk = i & 15, jl = i >> 4;
                    int grow = u0g + jl;
                    int k = kb + kk;
                    float v = (k < K1) ? Wih[(size_t)grow*K1 + k]
                                       : Whh[(size_t)grow*NH + (k - K1)];
                    wsl[g*2128 + kk*133 + jl] = v;
                }
            }
        }
    }

    // ---- init h/c + gumbel noise ----
    for (int i = blk*NTHR + tid; i < 3*BB*NH; i += NBLK*NTHR) {
        int l = i / (BB*NH), r = i % (BB*NH), u = r % NH;
        const float* hs = (l == 0) ? h00 : (l == 1) ? h01 : h02;
        const float* cs = (l == 0) ? c00 : (l == 1) ? c01 : c02;
        d_h[l][r] = hs[u];
        d_c[l][r] = cs[u];
    }
    // JAX partitionable threefry: counter j -> (0, j), key (0,1), bits = y0^y1
    for (int j = blk*NTHR + tid; j < GN_TOTAL; j += NBLK*NTHR) {
        unsigned int x0 = 0u;
        unsigned int x1 = (unsigned int)j;
        const unsigned int k0 = 0u, k1 = 1u;
        const unsigned int k2 = 0x1BD11BDAu ^ k0 ^ k1;
        x0 += k0; x1 += k1;
#define TF_RND(r) { x0 += x1; x1 = (x1 << (r)) | (x1 >> (32-(r))); x1 ^= x0; }
        TF_RND(13) TF_RND(15) TF_RND(26) TF_RND(6)
        x0 += k1; x1 += k2 + 1u;
        TF_RND(17) TF_RND(29) TF_RND(16) TF_RND(24)
        x0 += k2; x1 += k0 + 2u;
        TF_RND(13) TF_RND(15) TF_RND(26) TF_RND(6)
        x0 += k0; x1 += k1 + 3u;
        TF_RND(17) TF_RND(29) TF_RND(16) TF_RND(24)
        x0 += k1; x1 += k2 + 4u;
        TF_RND(13) TF_RND(15) TF_RND(26) TF_RND(6)
        x0 += k2; x1 += k0 + 5u;
#undef TF_RND
        unsigned int bits = x0 ^ x1;
        float u = __uint_as_float((bits >> 9) | 0x3f800000u) - 1.0f;
        d_gn[j] = -logf(1e-10f - logf(u + 1e-10f));
    }
    gridbar();

    const int b_att = blk >> 1;
    const int sub   = blk & 1;

    for (int t = -1; t < TT; t++) {
        if (t >= 0) {
#pragma unroll
            for (int l = 0; l < 3; l++) {
                // ===== GEMM: 16 j-tiles x 8 K-splits, weights resident in smem =====
                {
                    const int split = blk & 7, jt = blk >> 3;
                    const int u0g = jt * 128;
                    const int K1 = (l == 0) ? 2*NC : NH;
                    const int Kchunk = (K1 + NH) >> 3;      // 96 or 128
                    const int kb0 = split * Kchunk;
                    const float* xin = (l == 0) ? d_x : d_h[l-1];
                    const float* hin = d_h[l];
                    const float* wsl = DS + WOFF[l];
                    float* xs = SCR;                 // [16][68]
                    const int tx = tid & 31, ty = tid >> 5;

                    ull a0[4], a1[4];
#pragma unroll
                    for (int jj = 0; jj < 4; jj++) { a0[jj] = 0ull; a1[jj] = 0ull; }

                    for (int kt = 0; kt < Kchunk; kt += 16) {
                        const int kb = kb0 + kt;
                        for (int i = tid; i < 1024; i += NTHR) {
                            int kk = i & 15, bb = i >> 4;
                            int k = kb + kk;
                            float v = (k < K1) ? xin[bb*K1 + k] : hin[bb*NH + (k - K1)];
                            xs[kk*XS_STRIDE + bb] = v;
                        }
                        __syncthreads();
                        const float* ws = wsl + (kt >> 4)*2128;
#pragma unroll
                        for (int kk = 0; kk < 16; kk++) {
                            float4 xv = *(float4*)(xs + kk*XS_STRIDE + ty*4);
                            ull x01 = pack2(xv.x, xv.y);
                            ull x23 = pack2(xv.z, xv.w);
#pragma unroll
                            for (int jj = 0; jj < 4; jj++) {
                                float wv = ws[kk*133 + jj*32 + tx];
                                ull ww = pack2(wv, wv);
                                ffma2(a0[jj], x01, ww);
                                ffma2(a1[jj], x23, ww);
                            }
                        }
                        __syncthreads();
                    }
                    float* gp = d_gp[split];
#pragma unroll
                    for (int jj = 0; jj < 4; jj++) {
                        int gate = u0g + jj*32 + tx;
                        float f0, f1, f2, f3;
                        unpack2(a0[jj], f0, f1);
                        unpack2(a1[jj], f2, f3);
                        gp[(size_t)(ty*4 + 0)*G4 + gate] = f0;
                        gp[(size_t)(ty*4 + 1)*G4 + gate] = f1;
                        gp[(size_t)(ty*4 + 2)*G4 + gate] = f2;
                        gp[(size_t)(ty*4 + 3)*G4 + gate] = f3;
                    }
                }
                gridbar();
                // ===== cell: combine 8 partials + bias + nonlinearity =====
                {
                    const int idx = blk*NTHR + tid;
                    if (idx < BB*NH) {
                        const int bb = idx >> 9, u = idx & 511;
                        const float* bih = BihA[l];
                        const float* bhh = BhhA[l];
                        float gi = bih[u]        + bhh[u];
                        float gf = bih[u + NH]   + bhh[u + NH];
                        float gg = bih[u + 2*NH] + bhh[u + 2*NH];
                        float go = bih[u + 3*NH] + bhh[u + 3*NH];
#pragma unroll
                        for (int sp = 0; sp < 8; sp++) {
                            const float* gp = d_gp[sp] + (size_t)bb*G4;
                            gi += gp[u];
                            gf += gp[u + NH];
                            gg += gp[u + 2*NH];
                            go += gp[u + 3*NH];
                        }
                        float si = 1.0f / (1.0f + expf(-gi));
                        float sf = 1.0f / (1.0f + expf(-gf));
                        float so = 1.0f / (1.0f + expf(-go));
                        float cn = sf * d_c[l][idx] + si * tanhf(gg);
                        d_c[l][idx] = cn;
                        d_h[l][idx] = so * tanhf(cn);
                    }
                }
                gridbar();
            }
        }

        const int len   = lens[b_att];
        const int h0l   = len >> 1;
        const int begin = sub ? h0l : 0;
        const int cnt   = sub ? (len - h0l) : h0l;    // 512..1024, balanced
        const float* h3 = d_h[2] + (size_t)b_att*NH;

        // ===== attention: q-proj + energies + local softmax + ctx partial =====
        {
            float* q   = SCR;
            float* en  = SCR + 128;    // local exp/energy cache, [0, cnt)
            float* red = SCR + 1152;
            float* cp  = SCR + 1200;

            for (int d = w; d < NC; d += NW) {
                float p = 0.f;
                const float* wr = wq + (size_t)d*NH;
#pragma unroll 4
                for (int i = lane; i < NH; i += 32) p = fmaf(h3[i], wr[i], p);
                WARP_RED_SUM(p);
                if (lane == 0) q[d] = p + bq[d];
            }
            __syncthreads();
            float4 q4 = ((const float4*)q)[lane];
            const float4* kp = (const float4*)(keys + (size_t)b_att*SS*NC)
                               + (size_t)begin*32 + lane;
            float bmax = -1e30f;
            // warp w: rows base = ib*128 + w*8 .. +8, 8 loads in flight
            for (int ib = 0; ib < 8; ib++) {
                const int base = ib*128 + w*8;
                float4 kv[8];
#pragma unroll
                for (int j = 0; j < 8; j++) {
                    int r = base + j;
                    kv[j] = (r < cnt) ? __ldcs(kp + (size_t)r*32)
                                      : make_float4(0.f, 0.f, 0.f, 0.f);
                }
#pragma unroll
                for (int j = 0; j < 8; j++) {
                    int r = base + j;
                    float p = fmaf(q4.x, kv[j].x, fmaf(q4.y, kv[j].y,
                              fmaf(q4.z, kv[j].z, q4.w*kv[j].w)));
                    WARP_RED_SUM(p);
                    if (r < cnt) {
                        if (lane == 0) en[r] = p;
                        bmax = fmaxf(bmax, p);
                    }
                }
            }
            if (lane == 0) red[w] = bmax;
            __syncthreads();
            if (tid == 0) {
                float m = red[0];
                for (int i = 1; i < NW; i++) m = fmaxf(m, red[i]);
                red[16] = m;
            }
            __syncthreads();
            const float m_loc = red[16];

            // exp + local sum + ctx partial (8 loads in flight, 2 accumulators)
            const float4* vp = (const float4*)(values + (size_t)b_att*SS*NC)
                               + (size_t)begin*32 + lane;
            float4 ca0 = make_float4(0.f, 0.f, 0.f, 0.f);
            float4 ca1 = make_float4(0.f, 0.f, 0.f, 0.f);
            float ps = 0.f;
            for (int ib = 0; ib < 8; ib++) {
                const int base = ib*128 + w*8;
                float4 vv[8];
                float ee[8];
#pragma unroll
                for (int j = 0; j < 8; j++) {
                    int r = base + j;
                    vv[j] = (r < cnt) ? __ldcs(vp + (size_t)r*32)
                                      : make_float4(0.f, 0.f, 0.f, 0.f);
                }
#pragma unroll
                for (int j = 0; j < 8; j++) {
                    int r = base + j;
                    float e = (r < cnt) ? expf(en[r] - m_loc) : 0.f;
                    ee[j] = e;
                    ps += e;
                }
                if (lane == 0) {
#pragma unroll
                    for (int j = 0; j < 8; j++) {
                        int r = base + j;
                        if (r < cnt) en[r] = ee[j];
                    }
                }
#pragma unroll
                for (int j = 0; j < 8; j++) {
                    if (j & 1) {
                        ca1.x = fmaf(ee[j], vv[j].x, ca1.x);
                        ca1.y = fmaf(ee[j], vv[j].y, ca1.y);
                        ca1.z = fmaf(ee[j], vv[j].z, ca1.z);
                        ca1.w = fmaf(ee[j], vv[j].w, ca1.w);
                    } else {
                        ca0.x = fmaf(ee[j], vv[j].x, ca0.x);
                        ca0.y = fmaf(ee[j], vv[j].y, ca0.y);
                        ca0.z = fmaf(ee[j], vv[j].z, ca0.z);
                        ca0.w = fmaf(ee[j], vv[j].w, ca0.w);
                    }
                }
            }
            float4 ca = make_float4(ca0.x + ca1.x, ca0.y + ca1.y,
                                    ca0.z + ca1.z, ca0.w + ca1.w);
            if (lane == 0) red[w] = ps;
            ((float4*)cp)[w*32 + lane] = ca;
            __syncthreads();
            if (tid == 0) {
                float sm = 0.f;
                for (int i = 0; i < NW; i++) sm += red[i];
                d_psum[2*b_att + sub] = sm;
                d_pmax[2*b_att + sub] = m_loc;
            }
            if (tid < NC) {
                float cv = 0.f;
#pragma unroll
                for (int i = 0; i < NW; i++) cv += cp[i*128 + tid];
                d_ctxp[sub][b_att*NC + tid] = cv;
            }
        }
        gridbar();

        // ===== finalize: rescale + att write + ctx + out head + pack x =====
        {
            float m0 = d_pmax[2*b_att], m1 = d_pmax[2*b_att + 1];
            float m = fmaxf(m0, m1);
            float e0 = expf(m0 - m), e1 = expf(m1 - m);
            float total = d_psum[2*b_att]*e0 + d_psum[2*b_att + 1]*e1;
            float inv = 1.0f / total;
            float f = ((sub == 0) ? e0 : e1) * inv;
            float* en = SCR + 128;
            if (t >= 0) {
                float* ao = att_out + ((size_t)t*BB + b_att)*SS;
                for (int i = tid; i < cnt; i += NTHR)
                    __stcs(ao + begin + i, en[i] * f);
                // zero-fill masked region [len, SS), split between the pair
                int zlen  = SS - len;
                int zhalf = zlen >> 1;
                int zb    = len + sub*zhalf;
                int zc    = sub ? (zlen - zhalf) : zhalf;
                for (int i = tid; i < zc; i += NTHR)
                    __stcs(ao + zb + i, 0.f);
            }
            if (sub == 0) {
                float* ctxs = SCR + 3248;
                float* z    = SCR + 3392;
                float* lg   = SCR + 3536;
                if (tid < NC) {
                    float cv = (d_ctxp[0][b_att*NC + tid]*e0
                              + d_ctxp[1][b_att*NC + tid]*e1) * inv;
                    ctxs[tid] = cv;
                    d_x[b_att*2*NC + NC + tid] = cv;
                    if (t + 1 < TT) {
                        int tok = inputs[(size_t)b_att*TT + (t + 1)];
                        d_x[b_att*2*NC + tid] = emb[(size_t)tok*NC + tid];
                    }
                }
                __syncthreads();
                if (t >= 0) {
                    for (int d = w; d < NC; d += NW) {
                        float p = 0.f;
                        const float* wr = wc + (size_t)d*(NH + NC);
#pragma unroll 4
                        for (int i = lane; i < NH + NC; i += 32) {
                            float xv = (i < NH) ? h3[i] : ctxs[i - NH];
                            p = fmaf(xv, wr[i], p);
                        }
                        WARP_RED_SUM(p);
                        if (lane == 0) {
                            float a = p + bc[d];
                            z[d] = (a > 0.f) ? a : 0.01f * a;
                        }
                    }
                    __syncthreads();
                    if (tid < NINP) {
                        float lv = b_out[tid];
                        const float* er = emb + (size_t)tid*NC;
#pragma unroll 4
                        for (int k = 0; k < NC; k++) lv = fmaf(z[k], er[k], lv);
                        logits_out[((size_t)t*BB + b_att)*NINP + tid] = lv;
                        lg[tid] = lv + d_gn[((size_t)t*BB + b_att)*NINP + tid];
                    }
                    __syncthreads();
                    if (tid == 0) {
                        float best = lg[0]; int bi = 0;
                        for (int i = 1; i < NINP; i++)
                            if (lg[i] > best) { best = lg[i]; bi = i; }
                        gen_out[(size_t)t*BB + b_att] = (float)bi;
                    }
                }
            }
        }
        gridbar();
    }
}

// ---------------- launch: ONE graph node ----------------
extern "C" void kernel_launch(void* const* d_in, const int* in_sizes, int n_in,
                              void* d_out, int out_size)
{
    const float* keys   = (const float*)d_in[0];
    const float* values = (const float*)d_in[1];
    const int*   lens   = (const int*)d_in[2];
    const int*   inputs = (const int*)d_in[3];
    const float* emb    = (const float*)d_in[4];
    const float* wq     = (const float*)d_in[5];
    const float* bq     = (const float*)d_in[6];
    const float* wc     = (const float*)d_in[7];
    const float* bc     = (const float*)d_in[8];
    const float* b_out  = (const float*)d_in[9];

    float* O = (float*)d_out;
    float* logits_out = O;
    float* att_out    = O + (size_t)TT*BB*NINP;
    float* gen_out    = att_out + (size_t)TT*BB*SS;

    cudaFuncSetAttribute(decoder_persistent,
                         cudaFuncAttributeMaxDynamicSharedMemorySize, SMEM_BYTES);

    decoder_persistent<<<NBLK, NTHR, SMEM_BYTES>>>(
        keys, values, lens, inputs, emb, wq, bq, wc, bc, b_out,
        (const float*)d_in[10], (const float*)d_in[11], (const float*)d_in[12],
        (const float*)d_in[13], (const float*)d_in[14], (const float*)d_in[15],
        (const float*)d_in[16], (const float*)d_in[17], (const float*)d_in[18],
        (const float*)d_in[19], (const float*)d_in[20], (const float*)d_in[21],
        (const float*)d_in[22], (const float*)d_in[23], (const float*)d_in[24],
        (const float*)d_in[25], (const float*)d_in[26], (const float*)d_in[27],
        logits_out, att_out, gen_out);
}

// round 16
// speedup vs baseline: 1.5904x; 1.0593x over previous
#include <cuda_runtime.h>
#include <math.h>

#define BB 64
#define SS 2048
#define NC 128
#define NH 512
#define NINP 34
#define TT 400
#define G4 (4*NH)
#define NBLK 128
#define NTHR 512
#define NW 16
#define GN_TOTAL (TT*BB*NINP)
#define XS_STRIDE 68   // 272 B rows: 16B-aligned float4 reads

// persistent-weight smem layout (floats)
#define W0_OFF 0        // layer0: 6 groups x 16x133 = 12768
#define W1_OFF 12768    // layer1: 8 groups x 16x133 = 17024
#define W2_OFF 29792    // layer2: 8 groups x 16x133 = 17024
#define SCR_OFF 46816   // phase scratch (xs double buffer / attention), 3584 floats
#define SMEM_FLOATS (SCR_OFF + 3584)
#define SMEM_BYTES (SMEM_FLOATS * 4)

typedef unsigned long long ull;

// ---------------- device scratch (static, no runtime allocs) ----------------
__device__ float d_h[3][BB*NH];
__device__ float d_c[3][BB*NH];
__device__ float d_gp[8][BB*G4];      // per-K-split GEMM partials
__device__ float d_x[BB*2*NC];        // [emb[tok], ctx] per b
__device__ float d_pmax[BB*2];
__device__ float d_psum[BB*2];
__device__ float d_ctxp[2][BB*NC];
__device__ float d_gn[GN_TOTAL];
__device__ unsigned int bar_cnt;       // zero-init; returns to 0 every launch
__device__ unsigned int bar_gen;       // monotonic across replays
__device__ unsigned int d_pflag[BB][2];// pair sync flags (monotonic)

// ---------------- packed f32x2 helpers (Blackwell FFMA2) ----------------
__device__ __forceinline__ ull pack2(float lo, float hi) {
    ull r;
    asm("mov.b64 %0, {%1, %2};" : "=l"(r) : "r"(__float_as_uint(lo)), "r"(__float_as_uint(hi)));
    return r;
}
__device__ __forceinline__ void unpack2(ull v, float &lo, float &hi) {
    unsigned int a, b;
    asm("mov.b64 {%0, %1}, %2;" : "=r"(a), "=r"(b) : "l"(v));
    lo = __uint_as_float(a); hi = __uint_as_float(b);
}
__device__ __forceinline__ void ffma2(ull &d, ull a, ull b) {
    asm("fma.rn.f32x2 %0, %1, %2, %0;" : "+l"(d) : "l"(a), "l"(b));
}
__device__ __forceinline__ void l2prefetch(const void* p) {
    asm volatile("prefetch.global.L2 [%0];" :: "l"(p));
}

// ---------------- software grid barrier (all 128 CTAs resident) ----------------
__device__ __forceinline__ void gridbar() {
    __syncthreads();
    __threadfence();            // release
    __syncthreads();
    if (threadIdx.x == 0) {
        unsigned int g = *(volatile unsigned int*)&bar_gen;
        if (atomicAdd(&bar_cnt, 1u) == NBLK - 1u) {
            *(volatile unsigned int*)&bar_cnt = 0u;
            __threadfence();
            atomicAdd(&bar_gen, 1u);
        } else {
            while (*(volatile unsigned int*)&bar_gen == g) { __nanosleep(64); }
        }
        __threadfence();        // acquire
    }
    __syncthreads();
}

#define WARP_RED_SUM(p) { _Pragma("unroll") for (int _o = 16; _o; _o >>= 1) (p) += __shfl_xor_sync(0xffffffffu, (p), _o); }

extern __shared__ float DS[];

__global__ void __launch_bounds__(NTHR) decoder_persistent(
    const float* __restrict__ keys, const float* __restrict__ values,
    const int* __restrict__ lens, const int* __restrict__ inputs,
    const float* __restrict__ emb,
    const float* __restrict__ wq, const float* __restrict__ bq,
    const float* __restrict__ wc, const float* __restrict__ bc,
    const float* __restrict__ b_out,
    const float* __restrict__ w0ih, const float* __restrict__ w0hh,
    const float* __restrict__ b0ih, const float* __restrict__ b0hh,
    const float* __restrict__ h00, const float* __restrict__ c00,
    const float* __restrict__ w1ih, const float* __restrict__ w1hh,
    const float* __restrict__ b1ih, const float* __restrict__ b1hh,
    const float* __restrict__ h01, const float* __restrict__ c01,
    const float* __restrict__ w2ih, const float* __restrict__ w2hh,
    const float* __restrict__ b2ih, const float* __restrict__ b2hh,
    const float* __restrict__ h02, const float* __restrict__ c02,
    float* __restrict__ logits_out, float* __restrict__ att_out,
    float* __restrict__ gen_out)
{
    // DS: [0..46816) persistent weights; SCR = DS+46816 (3584 floats):
    // GEMM: xs0 = SCR[0..1088), xs1 = SCR[1088..2176)
    // ATT:  q = SCR[0..128), en = SCR[128..1152), red = SCR[1152..1169),
    //       cp = SCR[1200..3248), ctxs = SCR[3248..3376), z = SCR[3392..3520), lg = SCR[3536..)
    float* SCR = DS + SCR_OFF;
    const int blk = blockIdx.x, tid = threadIdx.x;
    const int w = tid >> 5, lane = tid & 31;

    const float* WihA[3] = {w0ih, w1ih, w2ih};
    const float* WhhA[3] = {w0hh, w1hh, w2hh};
    const float* BihA[3] = {b0ih, b1ih, b2ih};
    const float* BhhA[3] = {b0hh, b1hh, b2hh};
    const int WOFF[3] = {W0_OFF, W1_OFF, W2_OFF};

    // ---- preload this CTA's weight slices into persistent smem (once) ----
    {
        const int split = blk & 7, jt = blk >> 3;
        const int u0g = jt * 128;
#pragma unroll
        for (int l = 0; l < 3; l++) {
            const int K1 = (l == 0) ? 2*NC : NH;
            const int Kchunk = (K1 + NH) >> 3;       // 96 or 128
            const int kb0 = split * Kchunk;
            const float* Wih = WihA[l];
            const float* Whh = WhhA[l];
            float* wsl = DS + WOFF[l];
            for (int g = 0; g < (Kchunk >> 4); g++) {
                const int kb = kb0 + g*16;
                for (int i = tid; i < 2048; i += NTHR) {
                    int kk = i & 15, jl = i >> 4;
                    int grow = u0g + jl;
                    int k = kb + kk;
                    float v = (k < K1) ? Wih[(size_t)grow*K1 + k]
                                       : Whh[(size_t)grow*NH + (k - K1)];
                    wsl[g*2128 + kk*133 + jl] = v;
                }
            }
        }
    }

    // ---- init h/c + gumbel noise ----
    for (int i = blk*NTHR + tid; i < 3*BB*NH; i += NBLK*NTHR) {
        int l = i / (BB*NH), r = i % (BB*NH), u = r % NH;
        const float* hs = (l == 0) ? h00 : (l == 1) ? h01 : h02;
        const float* cs = (l == 0) ? c00 : (l == 1) ? c01 : c02;
        d_h[l][r] = hs[u];
        d_c[l][r] = cs[u];
    }
    // JAX partitionable threefry: counter j -> (0, j), key (0,1), bits = y0^y1
    for (int j = blk*NTHR + tid; j < GN_TOTAL; j += NBLK*NTHR) {
        unsigned int x0 = 0u;
        unsigned int x1 = (unsigned int)j;
        const unsigned int k0 = 0u, k1 = 1u;
        const unsigned int k2 = 0x1BD11BDAu ^ k0 ^ k1;
        x0 += k0; x1 += k1;
#define TF_RND(r) { x0 += x1; x1 = (x1 << (r)) | (x1 >> (32-(r))); x1 ^= x0; }
        TF_RND(13) TF_RND(15) TF_RND(26) TF_RND(6)
        x0 += k1; x1 += k2 + 1u;
        TF_RND(17) TF_RND(29) TF_RND(16) TF_RND(24)
        x0 += k2; x1 += k0 + 2u;
        TF_RND(13) TF_RND(15) TF_RND(26) TF_RND(6)
        x0 += k0; x1 += k1 + 3u;
        TF_RND(17) TF_RND(29) TF_RND(16) TF_RND(24)
        x0 += k1; x1 += k2 + 4u;
        TF_RND(13) TF_RND(15) TF_RND(26) TF_RND(6)
        x0 += k2; x1 += k0 + 5u;
#undef TF_RND
        unsigned int bits = x0 ^ x1;
        float u = __uint_as_float((bits >> 9) | 0x3f800000u) - 1.0f;
        d_gn[j] = -logf(1e-10f - logf(u + 1e-10f));
    }
    gridbar();
    // uniform epoch base for pair flags (monotonic across graph replays)
    const unsigned int pbase = *(volatile unsigned int*)&bar_gen;

    const int b_att = blk >> 1;
    const int sub   = blk & 1;

    for (int t = -1; t < TT; t++) {
        const int len   = lens[b_att];
        const int h0l   = len >> 1;
        const int begin = sub ? h0l : 0;
        const int cnt   = sub ? (len - h0l) : h0l;    // 512..1024, balanced

        if (t >= 0) {
#pragma unroll
            for (int l = 0; l < 3; l++) {
                // ===== GEMM: weights in smem, xs double-buffered, 1 sync/ktile =====
                {
                    const int split = blk & 7, jt = blk >> 3;
                    const int u0g = jt * 128;
                    const int K1 = (l == 0) ? 2*NC : NH;
                    const int Kchunk = (K1 + NH) >> 3;      // 96 or 128
                    const int NKT = Kchunk >> 4;            // 6 or 8
                    const int kb0 = split * Kchunk;
                    const float* xin = (l == 0) ? d_x : d_h[l-1];
                    const float* hin = d_h[l];
                    const float* wsl = DS + WOFF[l];
                    const int tx = tid & 31, ty = tid >> 5;
                    const int kk0 = tid & 15, bb0 = tid >> 4;      // elem tid
                    const int bb1 = bb0 + 32;                      // elem tid+512

                    ull a0[4], a1[4];
#pragma unroll
                    for (int jj = 0; jj < 4; jj++) { a0[jj] = 0ull; a1[jj] = 0ull; }

                    float ra, rb;
                    {
                        int k = kb0 + kk0;
                        ra = (k < K1) ? xin[bb0*K1 + k] : hin[bb0*NH + (k - K1)];
                        rb = (k < K1) ? xin[bb1*K1 + k] : hin[bb1*NH + (k - K1)];
                    }
                    for (int g = 0; g < NKT; g++) {
                        float* xsw = SCR + (g & 1)*1088;
                        xsw[kk0*XS_STRIDE + bb0] = ra;
                        xsw[kk0*XS_STRIDE + bb1] = rb;
                        __syncthreads();
                        if (g + 1 < NKT) {
                            int k = kb0 + (g + 1)*16 + kk0;
                            ra = (k < K1) ? xin[bb0*K1 + k] : hin[bb0*NH + (k - K1)];
                            rb = (k < K1) ? xin[bb1*K1 + k] : hin[bb1*NH + (k - K1)];
                        }
                        const float* ws = wsl + g*2128;
#pragma unroll
                        for (int kk = 0; kk < 16; kk++) {
                            float4 xv = *(float4*)(xsw + kk*XS_STRIDE + ty*4);
                            ull x01 = pack2(xv.x, xv.y);
                            ull x23 = pack2(xv.z, xv.w);
#pragma unroll
                            for (int jj = 0; jj < 4; jj++) {
                                float wv = ws[kk*133 + jj*32 + tx];
                                ull ww = pack2(wv, wv);
                                ffma2(a0[jj], x01, ww);
                                ffma2(a1[jj], x23, ww);
                            }
                        }
                    }
                    float* gp = d_gp[split];
#pragma unroll
                    for (int jj = 0; jj < 4; jj++) {
                        int gate = u0g + jj*32 + tx;
                        float f0, f1, f2, f3;
                        unpack2(a0[jj], f0, f1);
                        unpack2(a1[jj], f2, f3);
                        gp[(size_t)(ty*4 + 0)*G4 + gate] = f0;
                        gp[(size_t)(ty*4 + 1)*G4 + gate] = f1;
                        gp[(size_t)(ty*4 + 2)*G4 + gate] = f2;
                        gp[(size_t)(ty*4 + 3)*G4 + gate] = f3;
                    }
                }
                gridbar();
                // ===== cell (256 thr) + K/V L2-prefetch (other 256 thr) =====
                {
                    if (tid < 256) {
                        const int idx = blk*256 + tid;     // covers BB*NH exactly
                        const int bb = idx >> 9, u = idx & 511;
                        const float* bih = BihA[l];
                        const float* bhh = BhhA[l];
                        float gi = bih[u]        + bhh[u];
                        float gf = bih[u + NH]   + bhh[u + NH];
                        float gg = bih[u + 2*NH] + bhh[u + 2*NH];
                        float go = bih[u + 3*NH] + bhh[u + 3*NH];
#pragma unroll
                        for (int sp = 0; sp < 8; sp++) {
                            const float* gp = d_gp[sp] + (size_t)bb*G4;
                            gi += gp[u];
                            gf += gp[u + NH];
                            gg += gp[u + 2*NH];
                            go += gp[u + 3*NH];
                        }
                        float si = 1.0f / (1.0f + expf(-gi));
                        float sf = 1.0f / (1.0f + expf(-gf));
                        float so = 1.0f / (1.0f + expf(-go));
                        float cn = sf * d_c[l][bb*NH + u] + si * tanhf(gg);
                        d_c[l][bb*NH + u] = cn;
                        d_h[l][bb*NH + u] = so * tanhf(cn);
                    } else {
                        // warm L2 with this CTA's upcoming K/V attention rows
                        const char* kbase = (const char*)(keys
                                            + (size_t)b_att*SS*NC + (size_t)begin*NC);
                        const char* vbase = (const char*)(values
                                            + (size_t)b_att*SS*NC + (size_t)begin*NC);
                        const int klines = cnt*4;           // 128B lines of K
                        const int j0 = ((tid - 256) + l*256) * 11;
#pragma unroll
                        for (int q = 0; q < 11; q++) {
                            int ln = j0 + q;
                            if (ln < klines)
                                l2prefetch(kbase + (size_t)ln*128);
                            else if (ln < 2*klines)
                                l2prefetch(vbase + (size_t)(ln - klines)*128);
                        }
                    }
                }
                gridbar();
            }
        }

        const float* h3 = d_h[2] + (size_t)b_att*NH;

        // ===== attention: q-proj + energies + local softmax + ctx partial =====
        {
            float* q   = SCR;
            float* en  = SCR + 128;    // local exp/energy cache, [0, cnt)
            float* red = SCR + 1152;
            float* cp  = SCR + 1200;

            for (int d = w; d < NC; d += NW) {
                float p = 0.f;
                const float* wr = wq + (size_t)d*NH;
#pragma unroll 4
                for (int i = lane; i < NH; i += 32) p = fmaf(h3[i], wr[i], p);
                WARP_RED_SUM(p);
                if (lane == 0) q[d] = p + bq[d];
            }
            __syncthreads();
            float4 q4 = ((const float4*)q)[lane];
            const float4* kp = (const float4*)(keys + (size_t)b_att*SS*NC)
                               + (size_t)begin*32 + lane;
            float bmax = -1e30f;
            for (int ib = 0; ib < 8; ib++) {
                const int base = ib*128 + w*8;
                float4 kv[8];
#pragma unroll
                for (int j = 0; j < 8; j++) {
                    int r = base + j;
                    kv[j] = (r < cnt) ? __ldcs(kp + (size_t)r*32)
                                      : make_float4(0.f, 0.f, 0.f, 0.f);
                }
#pragma unroll
                for (int j = 0; j < 8; j++) {
                    int r = base + j;
                    float p = fmaf(q4.x, kv[j].x, fmaf(q4.y, kv[j].y,
                              fmaf(q4.z, kv[j].z, q4.w*kv[j].w)));
                    WARP_RED_SUM(p);
                    if (r < cnt) {
                        if (lane == 0) en[r] = p;
                        bmax = fmaxf(bmax, p);
                    }
                }
            }
            if (lane == 0) red[w] = bmax;
            __syncthreads();
            if (tid == 0) {
                float m = red[0];
                for (int i = 1; i < NW; i++) m = fmaxf(m, red[i]);
                red[16] = m;
            }
            __syncthreads();
            const float m_loc = red[16];

            const float4* vp = (const float4*)(values + (size_t)b_att*SS*NC)
                               + (size_t)begin*32 + lane;
            float4 ca0 = make_float4(0.f, 0.f, 0.f, 0.f);
            float4 ca1 = make_float4(0.f, 0.f, 0.f, 0.f);
            float ps = 0.f;
            for (int ib = 0; ib < 8; ib++) {
                const int base = ib*128 + w*8;
                float4 vv[8];
                float ee[8];
#pragma unroll
                for (int j = 0; j < 8; j++) {
                    int r = base + j;
                    vv[j] = (r < cnt) ? __ldcs(vp + (size_t)r*32)
                                      : make_float4(0.f, 0.f, 0.f, 0.f);
                }
#pragma unroll
                for (int j = 0; j < 8; j++) {
                    int r = base + j;
                    float e = (r < cnt) ? expf(en[r] - m_loc) : 0.f;
                    ee[j] = e;
                    ps += e;
                }
                if (lane == 0) {
#pragma unroll
                    for (int j = 0; j < 8; j++) {
                        int r = base + j;
                        if (r < cnt) en[r] = ee[j];
                    }
                }
#pragma unroll
                for (int j = 0; j < 8; j++) {
                    if (j & 1) {
                        ca1.x = fmaf(ee[j], vv[j].x, ca1.x);
                        ca1.y = fmaf(ee[j], vv[j].y, ca1.y);
                        ca1.z = fmaf(ee[j], vv[j].z, ca1.z);
                        ca1.w = fmaf(ee[j], vv[j].w, ca1.w);
                    } else {
                        ca0.x = fmaf(ee[j], vv[j].x, ca0.x);
                        ca0.y = fmaf(ee[j], vv[j].y, ca0.y);
                        ca0.z = fmaf(ee[j], vv[j].z, ca0.z);
                        ca0.w = fmaf(ee[j], vv[j].w, ca0.w);
                    }
                }
            }
            float4 ca = make_float4(ca0.x + ca1.x, ca0.y + ca1.y,
                                    ca0.z + ca1.z, ca0.w + ca1.w);
            if (lane == 0) red[w] = ps;
            ((float4*)cp)[w*32 + lane] = ca;
            __syncthreads();
            if (tid == 0) {
                float sm = 0.f;
                for (int i = 0; i < NW; i++) sm += red[i];
                d_psum[2*b_att + sub] = sm;
                d_pmax[2*b_att + sub] = m_loc;
            }
            if (tid < NC) {
                float cv = 0.f;
#pragma unroll
                for (int i = 0; i < NW; i++) cv += cp[i*128 + tid];
                d_ctxp[sub][b_att*NC + tid] = cv;
            }
            // zero-fill masked att_out region (independent of partner)
            if (t >= 0) {
                float* ao = att_out + ((size_t)t*BB + b_att)*SS;
                int zlen  = SS - len;
                int zhalf = zlen >> 1;
                int zb    = len + sub*zhalf;
                int zc    = sub ? (zlen - zhalf) : zhalf;
                for (int i = tid; i < zc; i += NTHR)
                    __stcs(ao + zb + i, 0.f);
            }
        }

        // ===== pair sync (only the 2 CTAs of this batch row) =====
        {
            const unsigned int seq = pbase + (unsigned int)(t + 2);
            __syncthreads();
            __threadfence();     // release pmax/psum/ctxp
            __syncthreads();
            if (tid == 0) {
                *(volatile unsigned int*)&d_pflag[b_att][sub] = seq;
                while (*(volatile unsigned int*)&d_pflag[b_att][1 - sub] < seq)
                    { __nanosleep(32); }
            }
            __syncthreads();
        }

        // ===== finalize: rescale + att write + ctx + out head + pack x =====
        {
            float m0 = __ldcg(&d_pmax[2*b_att]), m1 = __ldcg(&d_pmax[2*b_att + 1]);
            float m = fmaxf(m0, m1);
            float e0 = expf(m0 - m), e1 = expf(m1 - m);
            float total = __ldcg(&d_psum[2*b_att])*e0 + __ldcg(&d_psum[2*b_att + 1])*e1;
            float inv = 1.0f / total;
            float f = ((sub == 0) ? e0 : e1) * inv;
            float* en = SCR + 128;
            if (t >= 0) {
                float* ao = att_out + ((size_t)t*BB + b_att)*SS;
                for (int i = tid; i < cnt; i += NTHR)
                    __stcs(ao + begin + i, en[i] * f);
            }
            if (sub == 0) {
                float* ctxs = SCR + 3248;
                float* z    = SCR + 3392;
                float* lg   = SCR + 3536;
                if (tid < NC) {
                    float cv = (__ldcg(&d_ctxp[0][b_att*NC + tid])*e0
                              + __ldcg(&d_ctxp[1][b_att*NC + tid])*e1) * inv;
                    ctxs[tid] = cv;
                    d_x[b_att*2*NC + NC + tid] = cv;
                    if (t + 1 < TT) {
                        int tok = inputs[(size_t)b_att*TT + (t + 1)];
                        d_x[b_att*2*NC + tid] = emb[(size_t)tok*NC + tid];
                    }
                }
                __syncthreads();
                if (t >= 0) {
                    for (int d = w; d < NC; d += NW) {
                        float p = 0.f;
                        const float* wr = wc + (size_t)d*(NH + NC);
#pragma unroll 4
                        for (int i = lane; i < NH + NC; i += 32) {
                            float xv = (i < NH) ? h3[i] : ctxs[i - NH];
                            p = fmaf(xv, wr[i], p);
                        }
                        WARP_RED_SUM(p);
                        if (lane == 0) {
                            float a = p + bc[d];
                            z[d] = (a > 0.f) ? a : 0.01f * a;
                        }
                    }
                    __syncthreads();
                    if (tid < NINP) {
                        float lv = b_out[tid];
                        const float* er = emb + (size_t)tid*NC;
#pragma unroll 4
                        for (int k = 0; k < NC; k++) lv = fmaf(z[k], er[k], lv);
                        logits_out[((size_t)t*BB + b_att)*NINP + tid] = lv;
                        lg[tid] = lv + d_gn[((size_t)t*BB + b_att)*NINP + tid];
                    }
                    __syncthreads();
                    if (tid == 0) {
                        float best = lg[0]; int bi = 0;
                        for (int i = 1; i < NINP; i++)
                            if (lg[i] > best) { best = lg[i]; bi = i; }
                        gen_out[(size_t)t*BB + b_att] = (float)bi;
                    }
                }
            }
        }
        gridbar();
    }
}

// ---------------- launch: ONE graph node ----------------
extern "C" void kernel_launch(void* const* d_in, const int* in_sizes, int n_in,
                              void* d_out, int out_size)
{
    const float* keys   = (const float*)d_in[0];
    const float* values = (const float*)d_in[1];
    const int*   lens   = (const int*)d_in[2];
    const int*   inputs = (const int*)d_in[3];
    const float* emb    = (const float*)d_in[4];
    const float* wq     = (const float*)d_in[5];
    const float* bq     = (const float*)d_in[6];
    const float* wc     = (const float*)d_in[7];
    const float* bc     = (const float*)d_in[8];
    const float* b_out  = (const float*)d_in[9];

    float* O = (float*)d_out;
    float* logits_out = O;
    float* att_out    = O + (size_t)TT*BB*NINP;
    float* gen_out    = att_out + (size_t)TT*BB*SS;

    cudaFuncSetAttribute(decoder_persistent,
                         cudaFuncAttributeMaxDynamicSharedMemorySize, SMEM_BYTES);

    decoder_persistent<<<NBLK, NTHR, SMEM_BYTES>>>(
        keys, values, lens, inputs, emb, wq, bq, wc, bc, b_out,
        (const float*)d_in[10], (const float*)d_in[11], (const float*)d_in[12],
        (const float*)d_in[13], (const float*)d_in[14], (const float*)d_in[15],
        (const float*)d_in[16], (const float*)d_in[17], (const float*)d_in[18],
        (const float*)d_in[19], (const float*)d_in[20], (const float*)d_in[21],
        (const float*)d_in[22], (const float*)d_in[23], (const float*)d_in[24],
        (const float*)d_in[25], (const float*)d_in[26], (const float*)d_in[27],
        logits_out, att_out, gen_out);
}